// round 7
// baseline (speedup 1.0000x reference)
#include <cuda_runtime.h>
#include <cuda_bf16.h>

#define N_CTRL 64
#define N_EVAL 2001
#define DEG 3
#define INV_INTERNAL (1.0f / 61.0f)   // 60 internal knots at k/61, k=1..60

#define NGROUPS 500                   // groups of 4 v: v0 = 4i, covers v < 2000
#define VSPLIT 2
#define GPB ((NGROUPS + VSPLIT - 1) / VSPLIT)   // 250
#define TPB 256

// ---------------- device scratch (no allocations allowed) ----------------
__device__ float4 g_cp4[N_CTRL * N_CTRL];     // packed control points (xyz_)
__device__ float4 g_Bu[N_EVAL];
__device__ int    g_su[N_EVAL];
__device__ float4 g_Bv[N_EVAL];               // AoS basis (tail point)
__device__ int    g_sv[N_EVAL];
__device__ float4 g_W[5][NGROUPS];            // transposed shifted weights: g_W[j][i].k = W_j(v=4i+k)
__device__ int    g_ob[NGROUPS];              // group leader span base (sv(4i) - 3)

__device__ __forceinline__ float knotf(int j) {
    if (j <= DEG) return 0.0f;
    if (j >= N_CTRL) return 1.0f;
    return (float)(j - DEG) * INV_INTERNAL;
}

// span = clip(searchsorted(knots, t, 'right') - 1, p, n_ctrl-1), analytic
__device__ __forceinline__ int find_span(float t) {
    int k = (int)floorf(t * 61.0f);
    if (k < 0) k = 0;
    if (k > 60) k = 60;
    if (k < 60 && (float)(k + 1) * INV_INTERNAL <= t) ++k;
    if (k > 0  && (float)k * INV_INTERNAL > t)        --k;
    return DEG + k;
}

// Cox-de-Boor (NURBS book A2.2), p=3
__device__ __forceinline__ void basis_funcs(float u, int span, float N[4]) {
    float left[4], right[4];
    N[0] = 1.0f;
    #pragma unroll
    for (int j = 1; j <= DEG; ++j) {
        left[j]  = u - knotf(span + 1 - j);
        right[j] = knotf(span + j) - u;
        float saved = 0.0f;
        #pragma unroll
        for (int r = 0; r < j; ++r) {
            float temp = N[r] / (right[r + 1] + left[j - r]);
            N[r] = saved + right[r + 1] * temp;
            saved = left[j - r] * temp;
        }
        N[j] = saved;
    }
}

// ---------------- kernel 1: pack cp, spans+basis, shifted W5 ----------------
__global__ void nurbs_prep_kernel(const float* __restrict__ cp,
                                  const float* __restrict__ pu,
                                  const float* __restrict__ pv) {
    int i = blockIdx.x * blockDim.x + threadIdx.x;
    if (i < N_CTRL * N_CTRL) {
        g_cp4[i] = make_float4(cp[3 * i], cp[3 * i + 1], cp[3 * i + 2], 0.0f);
    }
    if (i < N_EVAL) {
        {   // u axis
            float u = pu[i];
            int s = find_span(u);
            float B[4];
            basis_funcs(u, s, B);
            g_Bu[i] = make_float4(B[0], B[1], B[2], B[3]);
            g_su[i] = s;
        }
        {   // v axis
            float v = pv[i];
            int s = find_span(v);
            float B[4];
            basis_funcs(v, s, B);
            g_Bv[i] = make_float4(B[0], B[1], B[2], B[3]);
            g_sv[i] = s;

            if (i < 4 * NGROUPS) {
                int vL = i & ~3;                    // group leader
                int sL = find_span(pv[vL]);
                int d  = s - sL;                    // 0 or 1 (span width >> 4 params)
                if (d < 0) d = 0;
                if (d > 1) d = 1;
                float W5[5] = {0.f, 0.f, 0.f, 0.f, 0.f};
                float B[4];
                basis_funcs(v, s, B);               // recompute (cheap) to keep scope simple
                W5[d + 0] = B[0];
                W5[d + 1] = B[1];
                W5[d + 2] = B[2];
                W5[d + 3] = B[3];
                int gi = i >> 2, k = i & 3;
                #pragma unroll
                for (int jw = 0; jw < 5; ++jw) {
                    ((float*)&g_W[jw][gi])[k] = W5[jw];
                }
                if (k == 0) g_ob[gi] = sL - DEG;    // <= 60
            }
        }
    }
}

// 48B contiguous store at per-block-uniform misalignment delta = 12*q mod 16
__device__ __forceinline__ void store48(float* dst, const float res[12], int q) {
    if (q == 0) {            // 16B aligned
        ((float4*)dst)[0] = make_float4(res[0], res[1], res[2], res[3]);
        ((float4*)dst)[1] = make_float4(res[4], res[5], res[6], res[7]);
        ((float4*)dst)[2] = make_float4(res[8], res[9], res[10], res[11]);
    } else if (q == 2) {     // delta = 8
        *(float2*)(dst)     = make_float2(res[0], res[1]);
        *(float4*)(dst + 2) = make_float4(res[2], res[3], res[4], res[5]);
        *(float4*)(dst + 6) = make_float4(res[6], res[7], res[8], res[9]);
        *(float2*)(dst + 10) = make_float2(res[10], res[11]);
    } else if (q == 1) {     // delta = 12
        dst[0] = res[0];
        *(float4*)(dst + 1) = make_float4(res[1], res[2], res[3], res[4]);
        *(float4*)(dst + 5) = make_float4(res[5], res[6], res[7], res[8]);
        *(float2*)(dst + 9) = make_float2(res[9], res[10]);
        dst[11] = res[11];
    } else {                 // q == 3, delta = 4
        dst[0] = res[0];
        *(float2*)(dst + 1) = make_float2(res[1], res[2]);
        *(float4*)(dst + 3) = make_float4(res[3], res[4], res[5], res[6]);
        *(float4*)(dst + 7) = make_float4(res[7], res[8], res[9], res[10]);
        dst[11] = res[11];
    }
}

// ---------------- kernel 2: eval. Block = 4 rows with u = q + 16*jq + 4*r ----------------
__global__ __launch_bounds__(TPB) void nurbs_eval_kernel(float* __restrict__ out) {
    __shared__ float4 s_curve[4][N_CTRL + 1];   // +1 pad column (zero)

    const int tid   = threadIdx.x;
    const int q     = blockIdx.y & 3;
    const int jq    = blockIdx.y >> 2;
    const int ubase = q + (jq << 4);            // rows ubase + 4r, all == q (mod 4)

    // prologue: u-collapse the 4 rows (tid -> (row r, ctrl col jj))
    {
        const int r  = tid >> 6;
        const int jj = tid & 63;
        const int u  = ubase + (r << 2);
        if (u < N_EVAL) {
            const float4 bu = g_Bu[u];
            const float4* base = g_cp4 + (g_su[u] - DEG) * N_CTRL + jj;
            float4 p0 = base[0];
            float4 p1 = base[N_CTRL];
            float4 p2 = base[2 * N_CTRL];
            float4 p3 = base[3 * N_CTRL];
            float4 c;
            c.x = bu.x * p0.x + bu.y * p1.x + bu.z * p2.x + bu.w * p3.x;
            c.y = bu.x * p0.y + bu.y * p1.y + bu.z * p2.y + bu.w * p3.y;
            c.z = bu.x * p0.z + bu.y * p1.z + bu.z * p2.z + bu.w * p3.z;
            c.w = 0.0f;
            s_curve[r][jj] = c;
        }
        if (tid < 4) s_curve[tid][N_CTRL] = make_float4(0.f, 0.f, 0.f, 0.f);
    }
    __syncthreads();

    // main: one group of 4 consecutive v per thread
    const int gstart = blockIdx.x * GPB;
    const int gend   = (gstart + GPB) < NGROUPS ? (gstart + GPB) : NGROUPS;
    const int gi     = gstart + tid;

    if (gi < gend) {
        const float4 W0 = g_W[0][gi];   // component k = weight for point v0+k
        const float4 W1 = g_W[1][gi];
        const float4 W2 = g_W[2][gi];
        const float4 W3 = g_W[3][gi];
        const float4 W4 = g_W[4][gi];
        const int    ob = g_ob[gi];

        #pragma unroll
        for (int r = 0; r < 4; ++r) {
            const int u = ubase + (r << 2);
            if (u < N_EVAL) {
                const float4 c0 = s_curve[r][ob + 0];
                const float4 c1 = s_curve[r][ob + 1];
                const float4 c2 = s_curve[r][ob + 2];
                const float4 c3 = s_curve[r][ob + 3];
                const float4 c4 = s_curve[r][ob + 4];
                float res[12];
                // point k=0..3 uses W*.x/.y/.z/.w
                res[0]  = W0.x*c0.x + W1.x*c1.x + W2.x*c2.x + W3.x*c3.x + W4.x*c4.x;
                res[1]  = W0.x*c0.y + W1.x*c1.y + W2.x*c2.y + W3.x*c3.y + W4.x*c4.y;
                res[2]  = W0.x*c0.z + W1.x*c1.z + W2.x*c2.z + W3.x*c3.z + W4.x*c4.z;
                res[3]  = W0.y*c0.x + W1.y*c1.x + W2.y*c2.x + W3.y*c3.x + W4.y*c4.x;
                res[4]  = W0.y*c0.y + W1.y*c1.y + W2.y*c2.y + W3.y*c3.y + W4.y*c4.y;
                res[5]  = W0.y*c0.z + W1.y*c1.z + W2.y*c2.z + W3.y*c3.z + W4.y*c4.z;
                res[6]  = W0.z*c0.x + W1.z*c1.x + W2.z*c2.x + W3.z*c3.x + W4.z*c4.x;
                res[7]  = W0.z*c0.y + W1.z*c1.y + W2.z*c2.y + W3.z*c3.y + W4.z*c4.y;
                res[8]  = W0.z*c0.z + W1.z*c1.z + W2.z*c2.z + W3.z*c3.z + W4.z*c4.z;
                res[9]  = W0.w*c0.x + W1.w*c1.x + W2.w*c2.x + W3.w*c3.x + W4.w*c4.x;
                res[10] = W0.w*c0.y + W1.w*c1.y + W2.w*c2.y + W3.w*c3.y + W4.w*c4.y;
                res[11] = W0.w*c0.z + W1.w*c1.z + W2.w*c2.z + W3.w*c3.z + W4.w*c4.z;
                float* dst = out + (size_t)u * (N_EVAL * 3) + (size_t)gi * 12;
                store48(dst, res, q);
            }
        }
    }

    // tail: v = 2000, one point per row (handled by x-block 0, threads 0..3)
    if (blockIdx.x == 0 && tid < 4) {
        const int u = ubase + (tid << 2);
        if (u < N_EVAL) {
            const float4 bv = g_Bv[N_EVAL - 1];
            const int    o  = g_sv[N_EVAL - 1] - DEG;
            const float4 c0 = s_curve[tid][o + 0];
            const float4 c1 = s_curve[tid][o + 1];
            const float4 c2 = s_curve[tid][o + 2];
            const float4 c3 = s_curve[tid][o + 3];
            float* dst = out + (size_t)u * (N_EVAL * 3) + (size_t)(N_EVAL - 1) * 3;
            dst[0] = bv.x * c0.x + bv.y * c1.x + bv.z * c2.x + bv.w * c3.x;
            dst[1] = bv.x * c0.y + bv.y * c1.y + bv.z * c2.y + bv.w * c3.y;
            dst[2] = bv.x * c0.z + bv.y * c1.z + bv.z * c2.z + bv.w * c3.z;
        }
    }
}

extern "C" void kernel_launch(void* const* d_in, const int* in_sizes, int n_in,
                              void* d_out, int out_size) {
    const float* cp = (const float*)d_in[0];   // [64,64,3]
    const float* pu = (const float*)d_in[1];   // [2001]
    const float* pv = (const float*)d_in[2];   // [2001]
    float* out = (float*)d_out;

    nurbs_prep_kernel<<<16, 256>>>(cp, pu, pv);   // 4096 threads covers cp pack + params

    // row quads: q = y&3, jq = y>>2 in [0,126) -> 504 y-blocks; x = v-chunk
    dim3 grid(VSPLIT, 4 * 126);
    nurbs_eval_kernel<<<grid, TPB>>>(out);
}

// round 8
// speedup vs baseline: 1.5132x; 1.5132x over previous
#include <cuda_runtime.h>
#include <cuda_bf16.h>

#define N_CTRL 64
#define N_EVAL 2001
#define DEG 3
#define INV_INTERNAL (1.0f / 61.0f)   // 60 internal knots at k/61, k=1..60

#define TPB 256
#define U_TILE 4
#define VSPLIT 2
#define VCHUNK 1001                   // ceil(2001/2)
#define KITER 4                       // ceil(VCHUNK / TPB)

// ---------------- device scratch (no allocations allowed) ----------------
__device__ float4 g_cp4[N_CTRL * N_CTRL];   // packed control points (xyz_)
__device__ float4 g_Bu[N_EVAL];
__device__ float4 g_Bv[N_EVAL];
__device__ int    g_su[N_EVAL];
__device__ int    g_sv[N_EVAL];

__device__ __forceinline__ float knotf(int j) {
    if (j <= DEG) return 0.0f;
    if (j >= N_CTRL) return 1.0f;
    return (float)(j - DEG) * INV_INTERNAL;
}

// span = clip(searchsorted(knots, t, 'right') - 1, p, n_ctrl-1), analytic
__device__ __forceinline__ int find_span(float t) {
    int k = (int)floorf(t * 61.0f);
    if (k < 0) k = 0;
    if (k > 60) k = 60;
    if (k < 60 && (float)(k + 1) * INV_INTERNAL <= t) ++k;
    if (k > 0  && (float)k * INV_INTERNAL > t)        --k;
    return DEG + k;
}

// Cox-de-Boor (NURBS book A2.2), p=3
__device__ __forceinline__ void basis_funcs(float u, int span, float N[4]) {
    float left[4], right[4];
    N[0] = 1.0f;
    #pragma unroll
    for (int j = 1; j <= DEG; ++j) {
        left[j]  = u - knotf(span + 1 - j);
        right[j] = knotf(span + j) - u;
        float saved = 0.0f;
        #pragma unroll
        for (int r = 0; r < j; ++r) {
            float temp = N[r] / (right[r + 1] + left[j - r]);
            N[r] = saved + right[r + 1] * temp;
            saved = left[j - r] * temp;
        }
        N[j] = saved;
    }
}

// ---------------- kernel 1: pack cp + spans/basis for both axes ----------------
__global__ void nurbs_prep_kernel(const float* __restrict__ cp,
                                  const float* __restrict__ pu,
                                  const float* __restrict__ pv) {
    int i = blockIdx.x * blockDim.x + threadIdx.x;
    if (i < N_CTRL * N_CTRL) {
        g_cp4[i] = make_float4(cp[3 * i], cp[3 * i + 1], cp[3 * i + 2], 0.0f);
    }
    if (i < N_EVAL) {
        {
            float u = pu[i];
            int s = find_span(u);
            float B[4];
            basis_funcs(u, s, B);
            g_Bu[i] = make_float4(B[0], B[1], B[2], B[3]);
            g_su[i] = s;
        }
        {
            float v = pv[i];
            int s = find_span(v);
            float B[4];
            basis_funcs(v, s, B);
            g_Bv[i] = make_float4(B[0], B[1], B[2], B[3]);
            g_sv[i] = s;
        }
    }
}

// ---------------- kernel 2: fused collapse + v-eval (R6 structure, MLP 8) ----------------
__global__ __launch_bounds__(TPB) void nurbs_eval_kernel(float* __restrict__ out) {
    __shared__ float4 s_curve[U_TILE][N_CTRL];   // 4 KB

    const int u0  = blockIdx.y * U_TILE;
    const int tid = threadIdx.x;
    const int nrows  = (N_EVAL - u0) < U_TILE ? (N_EVAL - u0) : U_TILE;
    const int vstart = blockIdx.x * VCHUNK;
    const int vend   = (vstart + VCHUNK) < N_EVAL ? (vstart + VCHUNK) : N_EVAL;

    // prologue: packed-cp u-collapse, tid -> (row r, ctrl col j); 256 = 4*64
    {
        const int r = tid >> 6;
        const int j = tid & 63;
        if (r < nrows) {
            const float4 bu = g_Bu[u0 + r];
            const float4* base = g_cp4 + (g_su[u0 + r] - DEG) * N_CTRL + j;
            const float4 p0 = base[0];
            const float4 p1 = base[N_CTRL];
            const float4 p2 = base[2 * N_CTRL];
            const float4 p3 = base[3 * N_CTRL];
            float4 c;
            c.x = bu.x * p0.x + bu.y * p1.x + bu.z * p2.x + bu.w * p3.x;
            c.y = bu.x * p0.y + bu.y * p1.y + bu.z * p2.y + bu.w * p3.y;
            c.z = bu.x * p0.z + bu.y * p1.z + bu.z * p2.z + bu.w * p3.z;
            c.w = 0.0f;
            s_curve[r][j] = c;
        }
    }
    __syncthreads();

    // batched parameter loads: 8 independent LDG in flight per thread
    float4 bv[KITER];
    int    o[KITER];
    #pragma unroll
    for (int k = 0; k < KITER; ++k) {
        int p  = vstart + k * TPB + tid;
        int pc = p < vend ? p : vend - 1;     // clamp (loads always valid)
        bv[k] = g_Bv[pc];
        o[k]  = g_sv[pc] - DEG;
    }

    // fully unrolled compute + guarded direct stores (proven pattern)
    #pragma unroll
    for (int k = 0; k < KITER; ++k) {
        const int p = vstart + k * TPB + tid;
        if (p < vend) {
            #pragma unroll
            for (int r = 0; r < U_TILE; ++r) {
                if (r < nrows) {
                    const float4 c0 = s_curve[r][o[k] + 0];
                    const float4 c1 = s_curve[r][o[k] + 1];
                    const float4 c2 = s_curve[r][o[k] + 2];
                    const float4 c3 = s_curve[r][o[k] + 3];
                    const float4 b  = bv[k];
                    float x = b.x * c0.x + b.y * c1.x + b.z * c2.x + b.w * c3.x;
                    float y = b.x * c0.y + b.y * c1.y + b.z * c2.y + b.w * c3.y;
                    float z = b.x * c0.z + b.y * c1.z + b.z * c2.z + b.w * c3.z;
                    float* dst = out + ((size_t)(u0 + r) * N_EVAL + p) * 3;
                    dst[0] = x;
                    dst[1] = y;
                    dst[2] = z;
                }
            }
        }
    }
}

extern "C" void kernel_launch(void* const* d_in, const int* in_sizes, int n_in,
                              void* d_out, int out_size) {
    const float* cp = (const float*)d_in[0];   // [64,64,3]
    const float* pu = (const float*)d_in[1];   // [2001]
    const float* pv = (const float*)d_in[2];   // [2001]
    float* out = (float*)d_out;

    nurbs_prep_kernel<<<16, 256>>>(cp, pu, pv);   // 4096 threads: cp pack + params
    dim3 grid(VSPLIT, (N_EVAL + U_TILE - 1) / U_TILE);
    nurbs_eval_kernel<<<grid, TPB>>>(out);
}

// round 9
// speedup vs baseline: 1.8548x; 1.2258x over previous
#include <cuda_runtime.h>
#include <cuda_bf16.h>

#define N_CTRL 64
#define N_EVAL 2001
#define DEG 3
#define INV_INTERNAL (1.0f / 61.0f)   // 60 internal knots at k/61, k=1..60

#define TPB 256
#define U_TILE 4
#define VSPLIT 2
#define VCHUNK 1001                   // ceil(2001/2)
#define KITER 4                       // ceil(VCHUNK / TPB)

__device__ __forceinline__ float knotf(int j) {
    if (j <= DEG) return 0.0f;
    if (j >= N_CTRL) return 1.0f;
    return (float)(j - DEG) * INV_INTERNAL;
}

// span = clip(searchsorted(knots, t, 'right') - 1, p, n_ctrl-1), analytic
__device__ __forceinline__ int find_span(float t) {
    int k = (int)floorf(t * 61.0f);
    if (k < 0) k = 0;
    if (k > 60) k = 60;
    if (k < 60 && (float)(k + 1) * INV_INTERNAL <= t) ++k;
    if (k > 0  && (float)k * INV_INTERNAL > t)        --k;
    return DEG + k;
}

// Cox-de-Boor (NURBS book A2.2), p=3. FAST=1 uses __fdividef (MUFU.RCP),
// rel err ~5e-7 per weight, far under the 1e-3 gate.
template <int FAST>
__device__ __forceinline__ void basis_funcs(float u, int span, float N[4]) {
    float left[4], right[4];
    N[0] = 1.0f;
    #pragma unroll
    for (int j = 1; j <= DEG; ++j) {
        left[j]  = u - knotf(span + 1 - j);
        right[j] = knotf(span + j) - u;
        float saved = 0.0f;
        #pragma unroll
        for (int r = 0; r < j; ++r) {
            float denom = right[r + 1] + left[j - r];
            float temp  = FAST ? __fdividef(N[r], denom) : (N[r] / denom);
            N[r] = saved + right[r + 1] * temp;
            saved = left[j - r] * temp;
        }
        N[j] = saved;
    }
}

// ---------------- single fused kernel ----------------
// Block: 4 u-rows x 1001-v chunk. Prologue computes u-basis inline and
// u-collapses control points into smem; main loop computes v-basis inline.
__global__ __launch_bounds__(TPB) void nurbs_kernel(const float* __restrict__ cp,
                                                    const float* __restrict__ pu,
                                                    const float* __restrict__ pv,
                                                    float* __restrict__ out) {
    __shared__ float4 s_curve[U_TILE][N_CTRL];   // 4 KB

    const int u0  = blockIdx.y * U_TILE;
    const int tid = threadIdx.x;
    const int nrows  = (N_EVAL - u0) < U_TILE ? (N_EVAL - u0) : U_TILE;
    const int vstart = blockIdx.x * VCHUNK;
    const int vend   = (vstart + VCHUNK) < N_EVAL ? (vstart + VCHUNK) : N_EVAL;

    // ---- prologue: inline u-basis + u-collapse; tid -> (row r, ctrl col j) ----
    {
        const int r = tid >> 6;       // 0..3
        const int j = tid & 63;       // 0..63
        if (r < nrows) {
            const float uu = pu[u0 + r];          // broadcast within 64-lane group
            const int   su = find_span(uu);
            float B[4];
            basis_funcs<0>(uu, su, B);            // exact division (once per block)
            const float* base = cp + ((su - DEG) * N_CTRL + j) * 3;
            float cx = 0.f, cy = 0.f, cz = 0.f;
            #pragma unroll
            for (int a = 0; a < 4; ++a) {
                const float* q = base + a * (N_CTRL * 3);
                cx += B[a] * q[0];
                cy += B[a] * q[1];
                cz += B[a] * q[2];
            }
            s_curve[r][j] = make_float4(cx, cy, cz, 0.f);
        }
    }
    __syncthreads();

    // ---- batched pv loads: independent LDGs in flight ----
    float pvv[KITER];
    #pragma unroll
    for (int k = 0; k < KITER; ++k) {
        int p  = vstart + k * TPB + tid;
        int pc = p < vend ? p : vend - 1;
        pvv[k] = pv[pc];
    }

    // ---- main: inline v-basis (fast div), 4 rows per point, direct stores ----
    #pragma unroll
    for (int k = 0; k < KITER; ++k) {
        const int p = vstart + k * TPB + tid;
        if (p < vend) {
            const int sv = find_span(pvv[k]);
            float B[4];
            basis_funcs<1>(pvv[k], sv, B);
            const int o = sv - DEG;
            #pragma unroll
            for (int r = 0; r < U_TILE; ++r) {
                if (r < nrows) {
                    const float4 c0 = s_curve[r][o + 0];
                    const float4 c1 = s_curve[r][o + 1];
                    const float4 c2 = s_curve[r][o + 2];
                    const float4 c3 = s_curve[r][o + 3];
                    float x = B[0] * c0.x + B[1] * c1.x + B[2] * c2.x + B[3] * c3.x;
                    float y = B[0] * c0.y + B[1] * c1.y + B[2] * c2.y + B[3] * c3.y;
                    float z = B[0] * c0.z + B[1] * c1.z + B[2] * c2.z + B[3] * c3.z;
                    float* dst = out + ((size_t)(u0 + r) * N_EVAL + p) * 3;
                    dst[0] = x;
                    dst[1] = y;
                    dst[2] = z;
                }
            }
        }
    }
}

extern "C" void kernel_launch(void* const* d_in, const int* in_sizes, int n_in,
                              void* d_out, int out_size) {
    const float* cp = (const float*)d_in[0];   // [64,64,3]
    const float* pu = (const float*)d_in[1];   // [2001]
    const float* pv = (const float*)d_in[2];   // [2001]
    float* out = (float*)d_out;

    dim3 grid(VSPLIT, (N_EVAL + U_TILE - 1) / U_TILE);   // (2, 501)
    nurbs_kernel<<<grid, TPB>>>(cp, pu, pv, out);
}